// round 14
// baseline (speedup 1.0000x reference)
#include <cuda_runtime.h>
#include <cuda_fp16.h>
#include <cuda_fp8.h>
#include <cstdint>
#include <cstddef>

#define NUc 100000
#define NTc 200000
#define Ec  1000000

typedef unsigned long long u64;
typedef unsigned int u32;
typedef unsigned short u16;

// ---------------- scratch (device globals; no allocation) ----------------
__device__ __align__(128) u32 g_huh[NUc*32];
__device__ __align__(128) u32 g_hth[NTc*32];
__device__ __align__(128) u32 g_mu0h[NUc*16];
__device__ __align__(128) u32 g_mu1h[NUc*16];
__device__ __align__(128) u32 g_mt0h[NTc*16];
__device__ __align__(128) u32 g_mt1h[NTc*16];

__device__ __align__(128) u32 g_wpk[13][2048];

__device__ int g_c_u2u[NUc];
__device__ int g_c_t2t[NTc];
__device__ int g_c_u2t_d[NTc];
__device__ int g_c_t2u_d[NUc];
__device__ int g_c_u2t_s[NUc];
__device__ int g_c_t2u_s[NTc];

__device__ float g_d_u2u[NUc];
__device__ float g_d_t2t[NTc];
__device__ float g_ds_u2t[NUc];
__device__ float g_dd_u2t[NTc];
__device__ float g_ds_t2u[NTc];
__device__ float g_dd_t2u[NUc];

__device__ int g_off_u2u[NUc+1];
__device__ int g_off_t2t[NTc+1];
__device__ int g_off_u2t[NTc+1];
__device__ int g_off_t2u[NUc+1];
__device__ int g_cur_u2u[NUc];
__device__ int g_cur_t2t[NTc];
__device__ int g_cur_u2t[NTc];
__device__ int g_cur_t2u[NUc];
__device__ int g_csr_u2u[Ec];
__device__ int g_csr_t2t[Ec];
__device__ int g_csr_u2t[Ec];
__device__ int g_csr_t2u[Ec];

__device__ float g_colsum[128];

// ---------------- helpers ----------------
__device__ __forceinline__ void mma_f16(float* c, u32 a0, u32 a1, u32 a2, u32 a3,
                                        u32 b0, u32 b1) {
    asm volatile(
        "mma.sync.aligned.m16n8k16.row.col.f32.f16.f16.f32 "
        "{%0,%1,%2,%3}, {%4,%5,%6,%7}, {%8,%9}, {%0,%1,%2,%3};"
        : "+f"(c[0]), "+f"(c[1]), "+f"(c[2]), "+f"(c[3])
        : "r"(a0), "r"(a1), "r"(a2), "r"(a3), "r"(b0), "r"(b1));
}
__device__ __forceinline__ void acc_h8(float* acc, uint4 v) {
    float2 f;
    f = __half22float2(*(__half2*)&v.x); acc[0] += f.x; acc[1] += f.y;
    f = __half22float2(*(__half2*)&v.y); acc[2] += f.x; acc[3] += f.y;
    f = __half22float2(*(__half2*)&v.z); acc[4] += f.x; acc[5] += f.y;
    f = __half22float2(*(__half2*)&v.w); acc[6] += f.x; acc[7] += f.y;
}
__device__ __forceinline__ uint4 h2add4(uint4 a, uint4 b) {
    uint4 r;
    *(__half2*)&r.x = __hadd2(*(__half2*)&a.x, *(__half2*)&b.x);
    *(__half2*)&r.y = __hadd2(*(__half2*)&a.y, *(__half2*)&b.y);
    *(__half2*)&r.z = __hadd2(*(__half2*)&a.z, *(__half2*)&b.z);
    *(__half2*)&r.w = __hadd2(*(__half2*)&a.w, *(__half2*)&b.w);
    return r;
}
__device__ __forceinline__ u16 pack2_e4m3(float c0, float c1) {
    return __nv_cvt_float2_to_fp8x2(make_float2(c0, c1), __NV_SATFINITE, __NV_E4M3);
}
__device__ __forceinline__ u32 fp8x2_to_h2(u16 v) {
    __half2_raw r = __nv_cvt_fp8x2_to_halfraw2(v, __NV_E4M3);
    return *(u32*)&r;
}
__device__ __forceinline__ uint4 fp8_widen8(uint2 v) {
    uint4 r;
    r.x = fp8x2_to_h2((u16)(v.x & 0xffff));
    r.y = fp8x2_to_h2((u16)(v.x >> 16));
    r.z = fp8x2_to_h2((u16)(v.y & 0xffff));
    r.w = fp8x2_to_h2((u16)(v.y >> 16));
    return r;
}
__device__ __forceinline__ u64 pack2(float a) {
    u64 r; asm("mov.b64 %0,{%1,%1};" : "=l"(r) : "f"(a)); return r;
}
__device__ __forceinline__ u64 pack2ab(float a, float b) {
    u64 r; asm("mov.b64 %0,{%1,%2};" : "=l"(r) : "f"(a), "f"(b)); return r;
}
__device__ __forceinline__ void fma2(u64& acc, u64 a, u64 w) {
    asm("fma.rn.f32x2 %0,%1,%2,%3;" : "=l"(acc) : "l"(a), "l"(w), "l"(acc));
}
__device__ __forceinline__ float2 unpack2(u64 v) {
    float2 f; asm("mov.b64 {%0,%1},%2;" : "=f"(f.x), "=f"(f.y) : "l"(v)); return f;
}

// ---------------- setup: pack all weights once (fragment order, fp16) ----------------
__global__ void packw_kernel(const float* __restrict__ Wtxn,
                             const float* __restrict__ convW) {
    int m = blockIdx.x;
    const float* W = (m == 0) ? Wtxn : convW + (size_t)(m - 1) * 4096;
    int t = threadIdx.x;
    for (int i = t; i < 1024; i += 256) {
        int kk = i >> 8, nt = (i >> 5) & 7, ln = i & 31;
        int col = nt * 8 + (ln >> 2);
        int k0 = kk * 16 + 2 * (ln & 3);
        __half2 lo = __floats2half2_rn(W[k0 * 64 + col], W[(k0 + 1) * 64 + col]);
        __half2 hi = __floats2half2_rn(W[(k0 + 8) * 64 + col], W[(k0 + 9) * 64 + col]);
        g_wpk[m][i * 2]     = *(u32*)&lo;
        g_wpk[m][i * 2 + 1] = *(u32*)&hi;
    }
}

// ---------------- setup: counts ----------------
__global__ void zero_cnt_kernel() {
    int i = blockIdx.x * blockDim.x + threadIdx.x;
    if (i < NUc) { g_c_u2u[i] = 0; g_c_u2t_s[i] = 0; g_c_t2u_d[i] = 0; }
    if (i < NTc) { g_c_t2t[i] = 0; g_c_u2t_d[i] = 0; g_c_t2u_s[i] = 0; }
    if (i < 128) g_colsum[i] = 0.f;
}

__global__ void count_kernel(const int* __restrict__ eu2u, const int* __restrict__ et2t,
                             const int* __restrict__ eu2t, const int* __restrict__ et2u) {
    int e = blockIdx.x * blockDim.x + threadIdx.x;
    if (e >= Ec) return;
    atomicAdd(&g_c_u2u[eu2u[Ec + e]], 1);
    atomicAdd(&g_c_t2t[et2t[Ec + e]], 1);
    atomicAdd(&g_c_u2t_d[eu2t[Ec + e]], 1);
    atomicAdd(&g_c_u2t_s[eu2t[e]],      1);
    atomicAdd(&g_c_t2u_d[et2u[Ec + e]], 1);
    atomicAdd(&g_c_t2u_s[et2u[e]],      1);
}

// ---------------- setup: 4 exclusive scans (one block each) ----------------
__global__ void scan4_kernel() {
    const int* cnt; int* off; int* cur; int n;
    switch (blockIdx.x) {
        case 0:  cnt = g_c_u2u;   off = g_off_u2u; cur = g_cur_u2u; n = NUc; break;
        case 1:  cnt = g_c_t2t;   off = g_off_t2t; cur = g_cur_t2t; n = NTc; break;
        case 2:  cnt = g_c_u2t_d; off = g_off_u2t; cur = g_cur_u2t; n = NTc; break;
        default: cnt = g_c_t2u_d; off = g_off_t2u; cur = g_cur_t2u; n = NUc; break;
    }
    __shared__ int sh[1024];
    int tid = threadIdx.x;
    int chunk = (n + 1023) >> 10;
    int start = tid * chunk;
    int end = min(start + chunk, n);
    int s = 0;
    for (int i = start; i < end; i++) s += cnt[i];
    sh[tid] = s;
    __syncthreads();
    for (int d = 1; d < 1024; d <<= 1) {
        int v = (tid >= d) ? sh[tid - d] : 0;
        __syncthreads();
        sh[tid] += v;
        __syncthreads();
    }
    int run = sh[tid] - s;
    for (int i = start; i < end; i++) { off[i] = run; cur[i] = run; run += cnt[i]; }
    if (start < n && end == n) off[n] = run;
}

// ---------------- setup: CSR fill ----------------
__global__ void fill_kernel(const int* __restrict__ eu2u, const int* __restrict__ et2t,
                            const int* __restrict__ eu2t, const int* __restrict__ et2u) {
    int e = blockIdx.x * blockDim.x + threadIdx.x;
    if (e >= Ec) return;
    int p;
    p = atomicAdd(&g_cur_u2u[eu2u[Ec + e]], 1); g_csr_u2u[p] = eu2u[e];
    p = atomicAdd(&g_cur_t2t[et2t[Ec + e]], 1); g_csr_t2t[p] = et2t[e];
    p = atomicAdd(&g_cur_u2t[eu2t[Ec + e]], 1); g_csr_u2t[p] = eu2t[e];
    p = atomicAdd(&g_cur_t2u[et2u[Ec + e]], 1); g_csr_t2u[p] = et2u[e];
}

__global__ void dinv_kernel() {
    int i = blockIdx.x * blockDim.x + threadIdx.x;
    if (i < NUc) {
        g_d_u2u[i] = rsqrtf((float)g_c_u2u[i] + 1.f);
        int cs = g_c_u2t_s[i]; g_ds_u2t[i] = (cs > 0) ? rsqrtf((float)cs) : 0.f;
        int cd = g_c_t2u_d[i]; g_dd_t2u[i] = (cd > 0) ? rsqrtf((float)cd) : 0.f;
    }
    if (i < NTc) {
        g_d_t2t[i] = rsqrtf((float)g_c_t2t[i] + 1.f);
        int cd = g_c_u2t_d[i]; g_dd_u2t[i] = (cd > 0) ? rsqrtf((float)cd) : 0.f;
        int cs = g_c_t2u_s[i]; g_ds_t2u[i] = (cs > 0) ? rsqrtf((float)cs) : 0.f;
    }
}

// ---------------- DUAL transform: 512 threads, split warp-groups ----------------
// warps 0-7 compute A@W0 (scaled sc0 -> O0), warps 8-15 compute A@W1 (sc1 -> O1).
// Shared A tile (128x32 u32 fp16, pitch 36); per-group weight smem; one staging pass.
__device__ __forceinline__ void dual512_gemm(const u32* __restrict__ Ah,
                                             const u32* __restrict__ Wp0,
                                             const u32* __restrict__ Wp1,
                                             const float* __restrict__ sc0,
                                             const float* __restrict__ sc1,
                                             u32* __restrict__ O0h,
                                             u32* __restrict__ O1h,
                                             int N, int tile) {
    extern __shared__ u32 smu[];
    u32* Wf0 = smu;             // 2048 u32
    u32* Wf1 = smu + 2048;      // 2048 u32
    u32* As  = smu + 4096;      // 128*36 u32; reused as staging
    int t = threadIdx.x;
    int lane = t & 31, wid = t >> 5;
    int wg = wid >> 3, wl = wid & 7;
    int fr = lane >> 2, fc = lane & 3;
    int row0 = tile * 128;

    // cooperative loads: weights (1 uint4 each matrix per thread) + A tile
    ((uint4*)Wf0)[t] = ((const uint4*)Wp0)[t];
    ((uint4*)Wf1)[t] = ((const uint4*)Wp1)[t];
    for (int i = t; i < 128 * 32; i += 512) {
        int r = i >> 5, c = i & 31;
        int gr = row0 + r;
        As[r * 36 + c] = (gr < N) ? Ah[((size_t)gr << 5) + c] : 0u;
    }
    __syncthreads();

    const u32* Wf = wg ? Wf1 : Wf0;
    int rbase = wl * 16;
    float acc[8][4];
#pragma unroll
    for (int nt = 0; nt < 8; nt++)
#pragma unroll
        for (int j = 0; j < 4; j++) acc[nt][j] = 0.f;

#pragma unroll
    for (int kk = 0; kk < 4; kk++) {
        int abase = (rbase + fr) * 36 + kk * 8 + fc;
        u32 a0 = As[abase];
        u32 a1 = As[abase + 8 * 36];
        u32 a2 = As[abase + 4];
        u32 a3 = As[abase + 8 * 36 + 4];
#pragma unroll
        for (int nt = 0; nt < 8; nt++) {
            uint2 b = *(const uint2*)&Wf[(size_t)(((kk << 3) + nt) << 5 | lane) * 2];
            mma_f16(acc[nt], a0, a1, a2, a3, b.x, b.y);
        }
    }

    // epilogue: both groups stage fp8 side-by-side in one pass
    int gr0 = row0 + rbase + fr, gr1 = gr0 + 8;
    const float* sc = wg ? sc1 : sc0;
    float s0 = sc[min(gr0, N - 1)], s1 = sc[min(gr1, N - 1)];
    __syncthreads();
    u16* st16 = (u16*)As;   // row pitch 72 u16; group0 cols 0..31, group1 cols 32..63
    int cb = wg * 32;
#pragma unroll
    for (int nt = 0; nt < 8; nt++) {
        st16[(rbase + fr) * 72 + cb + nt * 4 + fc] =
            pack2_e4m3(acc[nt][0] * s0, acc[nt][1] * s0);
        st16[(rbase + fr + 8) * 72 + cb + nt * 4 + fc] =
            pack2_e4m3(acc[nt][2] * s1, acc[nt][3] * s1);
    }
    __syncthreads();
    for (int i = t; i < 1024; i += 512) {
        int o = i >> 9, rem = i & 511;
        int r = rem >> 2, q = (rem & 3) << 2;
        int gr = row0 + r;
        if (gr < N) {
            u32* O = o ? O1h : O0h;
            *(uint4*)&O[((size_t)gr << 4) + q] = *(uint4*)&As[r * 36 + o * 16 + q];
        }
    }
}

#define GU_T ((NUc + 127) / 128)
#define GT_T ((NTc + 127) / 128)

__global__ void __launch_bounds__(512) transform_kernel(int l) {
    int b = blockIdx.x;
    int m = 1 + l * 4;
    if (b < GU_T) {
        dual512_gemm(g_huh, g_wpk[m + 0], g_wpk[m + 2], g_d_u2u, g_ds_u2t,
                     g_mu0h, g_mu1h, NUc, b);
    } else {
        dual512_gemm(g_hth, g_wpk[m + 1], g_wpk[m + 3], g_d_t2t, g_ds_t2u,
                     g_mt0h, g_mt1h, NTc, b - GU_T);
    }
}

// ---------------- embed_txn: fp16 MMA, 256 threads (single output) ----------------
__global__ void __launch_bounds__(256) embed_txn_kernel(const float* __restrict__ x,
                                                        const float* __restrict__ bias) {
    extern __shared__ u32 smu[];
    u32* Wf = smu;             // 2048 u32
    u32* As = smu + 2048;      // 128*36 u32
    int t = threadIdx.x;
    int lane = t & 31, wid = t >> 5;
    int fr = lane >> 2, fc = lane & 3;
    int row0 = blockIdx.x * 128;
    const int N = NTc;

    for (int i = t; i < 512; i += 256) ((uint4*)Wf)[i] = ((const uint4*)g_wpk[0])[i];
    for (int i = t; i < 128 * 32; i += 256) {
        int r = i >> 5, c = i & 31;
        int gr = row0 + r;
        u32 v = 0;
        if (gr < N) {
            const float2 f = *(const float2*)&x[((size_t)gr << 6) + 2 * c];
            __half2 h = __floats2half2_rn(f.x, f.y);
            v = *(u32*)&h;
        }
        As[r * 36 + c] = v;
    }
    __syncthreads();

    int rbase = wid * 16;
    float acc[8][4];
#pragma unroll
    for (int nt = 0; nt < 8; nt++)
#pragma unroll
        for (int j = 0; j < 4; j++) acc[nt][j] = 0.f;
#pragma unroll
    for (int kk = 0; kk < 4; kk++) {
        int abase = (rbase + fr) * 36 + kk * 8 + fc;
        u32 a0 = As[abase];
        u32 a1 = As[abase + 8 * 36];
        u32 a2 = As[abase + 4];
        u32 a3 = As[abase + 8 * 36 + 4];
#pragma unroll
        for (int nt = 0; nt < 8; nt++) {
            uint2 b = *(const uint2*)&Wf[(size_t)(((kk << 3) + nt) << 5 | lane) * 2];
            mma_f16(acc[nt], a0, a1, a2, a3, b.x, b.y);
        }
    }
    __syncthreads();
#pragma unroll
    for (int nt = 0; nt < 8; nt++) {
        float bx = bias[nt * 8 + 2 * fc], by = bias[nt * 8 + 2 * fc + 1];
        __half2 h0 = __floats2half2_rn(acc[nt][0] + bx, acc[nt][1] + by);
        __half2 h1 = __floats2half2_rn(acc[nt][2] + bx, acc[nt][3] + by);
        As[(rbase + fr) * 36 + nt * 4 + fc]     = *(u32*)&h0;
        As[(rbase + fr + 8) * 36 + nt * 4 + fc] = *(u32*)&h1;
    }
    __syncthreads();
    for (int i = t; i < 128 * 8; i += 256) {
        int r = i >> 3, q = (i & 7) << 2;
        int gr = row0 + r;
        if (gr < N) *(uint4*)&g_hth[((size_t)gr << 5) + q] = *(uint4*)&As[r * 36 + q];
    }
}

// ---------------- f32x2 embed for K=32 ----------------
__global__ void __launch_bounds__(256) embed_user_kernel(const float* __restrict__ A,
                                                         const float* __restrict__ W,
                                                         const float* __restrict__ b) {
    const int K = 32;
    __shared__ float Ws[K * 64];
    __shared__ float As[128 * (K + 1)];
    int t = threadIdx.x;
    for (int i = t; i < K * 64; i += 256) Ws[i] = W[i];
    int row0 = blockIdx.x * 128;
    for (int i = t; i < 128 * K; i += 256) {
        int r = i / K, c = i & (K - 1);
        int gr = row0 + r;
        As[r * (K + 1) + c] = (gr < NUc) ? A[(size_t)gr * K + c] : 0.f;
    }
    __syncthreads();
    int cg = t & 7, r0 = (t >> 3) << 2;
    u64 binit[4];
#pragma unroll
    for (int j = 0; j < 4; j++)
        binit[j] = pack2ab(b[(cg << 3) + (j << 1)], b[(cg << 3) + (j << 1) + 1]);
    u64 acc[4][4];
#pragma unroll
    for (int rr = 0; rr < 4; rr++)
#pragma unroll
        for (int j = 0; j < 4; j++) acc[rr][j] = binit[j];
#pragma unroll 4
    for (int k = 0; k < K; k++) {
        const float* wp = &Ws[(k << 6) + (cg << 3)];
        ulonglong2 wa = *(const ulonglong2*)wp;
        ulonglong2 wb = *(const ulonglong2*)(wp + 4);
#pragma unroll
        for (int rr = 0; rr < 4; rr++) {
            u64 a2 = pack2(As[(r0 + rr) * (K + 1) + k]);
            fma2(acc[rr][0], a2, wa.x);
            fma2(acc[rr][1], a2, wa.y);
            fma2(acc[rr][2], a2, wb.x);
            fma2(acc[rr][3], a2, wb.y);
        }
    }
#pragma unroll
    for (int rr = 0; rr < 4; rr++) {
        int gr = row0 + r0 + rr;
        if (gr < NUc) {
            float2 p0 = unpack2(acc[rr][0]), p1 = unpack2(acc[rr][1]);
            float2 p2 = unpack2(acc[rr][2]), p3 = unpack2(acc[rr][3]);
            __half2 h0 = __floats2half2_rn(p0.x, p0.y);
            __half2 h1 = __floats2half2_rn(p1.x, p1.y);
            __half2 h2 = __floats2half2_rn(p2.x, p2.y);
            __half2 h3 = __floats2half2_rn(p3.x, p3.y);
            uint4 pk;
            pk.x = *(u32*)&h0; pk.y = *(u32*)&h1; pk.z = *(u32*)&h2; pk.w = *(u32*)&h3;
            *(uint4*)&g_huh[((size_t)gr << 5) + (cg << 2)] = pk;
        }
    }
}

// ---------------- fused gather-aggregate + bias + relu (fp8 messages) ----------------
__device__ __forceinline__ void gather_loop(float* acc, const u32* __restrict__ m,
                                            const int* __restrict__ csr,
                                            int e, int end, int woff) {
    while (e < end && (e & 3)) {
        int s = __ldg(csr + e);
        acc_h8(acc, fp8_widen8(__ldg((const uint2*)(m + ((size_t)s << 4) + woff))));
        e++;
    }
    for (; e + 4 <= end; e += 4) {
        int4 s = __ldg((const int4*)(csr + e));
        uint2 v0 = __ldg((const uint2*)(m + ((size_t)s.x << 4) + woff));
        uint2 v1 = __ldg((const uint2*)(m + ((size_t)s.y << 4) + woff));
        uint2 v2 = __ldg((const uint2*)(m + ((size_t)s.z << 4) + woff));
        uint2 v3 = __ldg((const uint2*)(m + ((size_t)s.w << 4) + woff));
        uint4 x0 = fp8_widen8(v0), x1 = fp8_widen8(v1);
        uint4 x2 = fp8_widen8(v2), x3 = fp8_widen8(v3);
        uint4 tt = h2add4(h2add4(x0, x1), h2add4(x2, x3));
        acc_h8(acc, tt);
    }
    for (; e < end; e++) {
        int s = __ldg(csr + e);
        acc_h8(acc, fp8_widen8(__ldg((const uint2*)(m + ((size_t)s << 4) + woff))));
    }
}

__device__ __forceinline__ void agg_body(int idx,
                                         const u32* __restrict__ mA,
                                         const int* __restrict__ offA,
                                         const int* __restrict__ csrA,
                                         const float* __restrict__ dA,
                                         const u32* __restrict__ mB,
                                         const int* __restrict__ offB,
                                         const int* __restrict__ csrB,
                                         const float* __restrict__ dB,
                                         const float* __restrict__ bA,
                                         const float* __restrict__ bB,
                                         u32* __restrict__ Outh, int N) {
    int g = idx >> 3;
    if (g >= N) return;
    int q = idx & 7;
    int woff = q << 1;
    float a[8], b[8];
#pragma unroll
    for (int i = 0; i < 8; i++) { a[i] = 0.f; b[i] = 0.f; }
    acc_h8(a, fp8_widen8(__ldg((const uint2*)(mA + ((size_t)g << 4) + woff))));
    gather_loop(a, mA, csrA, offA[g], offA[g + 1], woff);
    gather_loop(b, mB, csrB, offB[g], offB[g + 1], woff);
    float da = dA[g], db = dB[g];
    int c0 = q << 3;
    float4 bAv0 = __ldg((const float4*)(bA + c0)), bAv1 = __ldg((const float4*)(bA + c0 + 4));
    float4 bBv0 = __ldg((const float4*)(bB + c0)), bBv1 = __ldg((const float4*)(bB + c0 + 4));
    float o0 = fmaxf(0.5f * (da * a[0] + db * b[0] + bAv0.x + bBv0.x), 0.f);
    float o1 = fmaxf(0.5f * (da * a[1] + db * b[1] + bAv0.y + bBv0.y), 0.f);
    float o2 = fmaxf(0.5f * (da * a[2] + db * b[2] + bAv0.z + bBv0.z), 0.f);
    float o3 = fmaxf(0.5f * (da * a[3] + db * b[3] + bAv0.w + bBv0.w), 0.f);
    float o4 = fmaxf(0.5f * (da * a[4] + db * b[4] + bAv1.x + bBv1.x), 0.f);
    float o5 = fmaxf(0.5f * (da * a[5] + db * b[5] + bAv1.y + bBv1.y), 0.f);
    float o6 = fmaxf(0.5f * (da * a[6] + db * b[6] + bAv1.z + bBv1.z), 0.f);
    float o7 = fmaxf(0.5f * (da * a[7] + db * b[7] + bAv1.w + bBv1.w), 0.f);
    __half2 h0 = __floats2half2_rn(o0, o1);
    __half2 h1 = __floats2half2_rn(o2, o3);
    __half2 h2 = __floats2half2_rn(o4, o5);
    __half2 h3 = __floats2half2_rn(o6, o7);
    uint4 pk;
    pk.x = *(u32*)&h0; pk.y = *(u32*)&h1; pk.z = *(u32*)&h2; pk.w = *(u32*)&h3;
    *(uint4*)&Outh[((size_t)g << 5) + (q << 2)] = pk;
}

#define AU_B ((NUc * 8 + 255) / 256)
#define AT_B ((NTc * 8 + 255) / 256)

__global__ void __launch_bounds__(256) agg_kernel(const float* __restrict__ B) {
    int b = blockIdx.x;
    if (b < AU_B) {
        agg_body(b * 256 + threadIdx.x,
                 g_mu0h, g_off_u2u, g_csr_u2u, g_d_u2u,
                 g_mt1h, g_off_t2u, g_csr_t2u, g_dd_t2u,
                 B + 0 * 64, B + 3 * 64, g_huh, NUc);
    } else {
        agg_body((b - AU_B) * 256 + threadIdx.x,
                 g_mt0h, g_off_t2t, g_csr_t2t, g_d_t2t,
                 g_mu1h, g_off_u2t, g_csr_u2t, g_dd_u2t,
                 B + 1 * 64, B + 2 * 64, g_hth, NTc);
    }
}

// ---------------- readout (fp16 h) ----------------
#define CS_BLOCKS 296
__global__ void colsum_kernel() {
    int b = blockIdx.x;
    if (b < CS_BLOCKS) {
        int t = b * blockDim.x + threadIdx.x;
        float s0 = 0.f, s1 = 0.f;
        const int n = NUc * 32;
        for (int i = t; i < n; i += CS_BLOCKS * 256) {
            u32 v = g_huh[i];
            float2 f = __half22float2(*(__half2*)&v);
            s0 += f.x; s1 += f.y;
        }
        int j = (t & 31) << 1;
        atomicAdd(&g_colsum[j], s0);
        atomicAdd(&g_colsum[j + 1], s1);
    } else {
        int t = (b - CS_BLOCKS) * blockDim.x + threadIdx.x;
        float s0 = 0.f, s1 = 0.f;
        const int n = NTc * 32;
        for (int i = t; i < n; i += CS_BLOCKS * 256) {
            u32 v = g_hth[i];
            float2 f = __half22float2(*(__half2*)&v);
            s0 += f.x; s1 += f.y;
        }
        int j = (t & 31) << 1;
        atomicAdd(&g_colsum[64 + j], s0);
        atomicAdd(&g_colsum[64 + j + 1], s1);
    }
}

__global__ void mlp_kernel(const float* __restrict__ W1, const float* __restrict__ b1,
                           const float* __restrict__ W2, const float* __restrict__ b2,
                           float* __restrict__ out) {
    __shared__ float x[64];
    __shared__ float y[64];
    int t = threadIdx.x;
    x[t] = 0.5f * (g_colsum[t] * (1.f / NUc) + g_colsum[64 + t] * (1.f / NTc));
    __syncthreads();
    float s = b1[t];
    for (int k = 0; k < 64; k++) s += x[k] * W1[k * 64 + t];
    y[t] = fmaxf(s, 0.f) * W2[t];
    __syncthreads();
    if (t == 0) {
        float o = b2[0];
        for (int j = 0; j < 64; j++) o += y[j];
        out[0] = 1.f / (1.f + expf(-o));
    }
}

// ---------------- launch ----------------
extern "C" void kernel_launch(void* const* d_in, const int* in_sizes, int n_in,
                              void* d_out, int out_size) {
    const float* x_user     = (const float*)d_in[0];
    const float* x_txn      = (const float*)d_in[1];
    const int*   ei_u2u     = (const int*)d_in[2];
    const int*   ei_t2t     = (const int*)d_in[3];
    const int*   ei_u2t     = (const int*)d_in[4];
    const int*   ei_t2u     = (const int*)d_in[5];
    const float* W_emb_user = (const float*)d_in[6];
    const float* b_emb_user = (const float*)d_in[7];
    const float* W_emb_txn  = (const float*)d_in[8];
    const float* b_emb_txn  = (const float*)d_in[9];
    const float* conv_W     = (const float*)d_in[10];
    const float* conv_b     = (const float*)d_in[11];
    const float* W1         = (const float*)d_in[12];
    const float* b1         = (const float*)d_in[13];
    const float* W2         = (const float*)d_in[14];
    const float* b2         = (const float*)d_in[15];
    float* out = (float*)d_out;

    const int SMEM_DUAL = (4096 + 128 * 36) * 4;   // 34816
    const int SMEM_SNGL = (2048 + 128 * 36) * 4;   // 26624

    packw_kernel<<<13, 256>>>(W_emb_txn, conv_W);
    zero_cnt_kernel<<<(NTc + 255) / 256, 256>>>();
    count_kernel<<<(Ec + 255) / 256, 256>>>(ei_u2u, ei_t2t, ei_u2t, ei_t2u);
    embed_txn_kernel<<<GT_T, 256, SMEM_SNGL>>>(x_txn, b_emb_txn);
    embed_user_kernel<<<(NUc + 127) / 128, 256>>>(x_user, W_emb_user, b_emb_user);
    scan4_kernel<<<4, 1024>>>();
    fill_kernel<<<(Ec + 255) / 256, 256>>>(ei_u2u, ei_t2t, ei_u2t, ei_t2u);
    dinv_kernel<<<(NTc + 255) / 256, 256>>>();

    // ---- layers ----
    for (int l = 0; l < 3; l++) {
        const float* B = conv_b + (size_t)l * 4 * 64;
        transform_kernel<<<GU_T + GT_T, 512, SMEM_DUAL>>>(l);
        agg_kernel<<<AU_B + AT_B, 256>>>(B);
    }

    // ---- readout ----
    colsum_kernel<<<2 * CS_BLOCKS, 256>>>();
    mlp_kernel<<<1, 64>>>(W1, b1, W2, b2, out);
}

// round 15
// speedup vs baseline: 1.0325x; 1.0325x over previous
#include <cuda_runtime.h>
#include <cuda_fp16.h>
#include <cuda_fp8.h>
#include <cstdint>
#include <cstddef>

#define NUc 100000
#define NTc 200000
#define Ec  1000000

typedef unsigned long long u64;
typedef unsigned int u32;
typedef unsigned short u16;

// ---------------- scratch (device globals; no allocation) ----------------
__device__ __align__(128) u32 g_huh[NUc*32];
__device__ __align__(128) u32 g_hth[NTc*32];
__device__ __align__(128) u32 g_mu0h[NUc*16];
__device__ __align__(128) u32 g_mu1h[NUc*16];
__device__ __align__(128) u32 g_mt0h[NTc*16];
__device__ __align__(128) u32 g_mt1h[NTc*16];

__device__ __align__(128) u32 g_wpk[13][2048];

__device__ int g_c_u2u[NUc];
__device__ int g_c_t2t[NTc];
__device__ int g_c_u2t_d[NTc];
__device__ int g_c_t2u_d[NUc];
__device__ int g_c_u2t_s[NUc];
__device__ int g_c_t2u_s[NTc];

__device__ float g_d_u2u[NUc];
__device__ float g_d_t2t[NTc];
__device__ float g_ds_u2t[NUc];
__device__ float g_dd_u2t[NTc];
__device__ float g_ds_t2u[NTc];
__device__ float g_dd_t2u[NUc];

__device__ int g_off_u2u[NUc+1];
__device__ int g_off_t2t[NTc+1];
__device__ int g_off_u2t[NTc+1];
__device__ int g_off_t2u[NUc+1];
__device__ int g_cur_u2u[NUc];
__device__ int g_cur_t2t[NTc];
__device__ int g_cur_u2t[NTc];
__device__ int g_cur_t2u[NUc];
__device__ int g_csr_u2u[Ec];
__device__ int g_csr_t2t[Ec];
__device__ int g_csr_u2t[Ec];
__device__ int g_csr_t2u[Ec];

__device__ float g_colsum[128];

// ---------------- helpers ----------------
__device__ __forceinline__ void mma_f16(float* c, u32 a0, u32 a1, u32 a2, u32 a3,
                                        u32 b0, u32 b1) {
    asm volatile(
        "mma.sync.aligned.m16n8k16.row.col.f32.f16.f16.f32 "
        "{%0,%1,%2,%3}, {%4,%5,%6,%7}, {%8,%9}, {%0,%1,%2,%3};"
        : "+f"(c[0]), "+f"(c[1]), "+f"(c[2]), "+f"(c[3])
        : "r"(a0), "r"(a1), "r"(a2), "r"(a3), "r"(b0), "r"(b1));
}
__device__ __forceinline__ void acc_h8(float* acc, uint4 v) {
    float2 f;
    f = __half22float2(*(__half2*)&v.x); acc[0] += f.x; acc[1] += f.y;
    f = __half22float2(*(__half2*)&v.y); acc[2] += f.x; acc[3] += f.y;
    f = __half22float2(*(__half2*)&v.z); acc[4] += f.x; acc[5] += f.y;
    f = __half22float2(*(__half2*)&v.w); acc[6] += f.x; acc[7] += f.y;
}
__device__ __forceinline__ uint4 h2add4(uint4 a, uint4 b) {
    uint4 r;
    *(__half2*)&r.x = __hadd2(*(__half2*)&a.x, *(__half2*)&b.x);
    *(__half2*)&r.y = __hadd2(*(__half2*)&a.y, *(__half2*)&b.y);
    *(__half2*)&r.z = __hadd2(*(__half2*)&a.z, *(__half2*)&b.z);
    *(__half2*)&r.w = __hadd2(*(__half2*)&a.w, *(__half2*)&b.w);
    return r;
}
__device__ __forceinline__ u16 pack2_e4m3(float c0, float c1) {
    return __nv_cvt_float2_to_fp8x2(make_float2(c0, c1), __NV_SATFINITE, __NV_E4M3);
}
__device__ __forceinline__ u32 fp8x2_to_h2(u16 v) {
    __half2_raw r = __nv_cvt_fp8x2_to_halfraw2(v, __NV_E4M3);
    return *(u32*)&r;
}
__device__ __forceinline__ uint4 fp8_widen8(uint2 v) {
    uint4 r;
    r.x = fp8x2_to_h2((u16)(v.x & 0xffff));
    r.y = fp8x2_to_h2((u16)(v.x >> 16));
    r.z = fp8x2_to_h2((u16)(v.y & 0xffff));
    r.w = fp8x2_to_h2((u16)(v.y >> 16));
    return r;
}
__device__ __forceinline__ u64 pack2(float a) {
    u64 r; asm("mov.b64 %0,{%1,%1};" : "=l"(r) : "f"(a)); return r;
}
__device__ __forceinline__ u64 pack2ab(float a, float b) {
    u64 r; asm("mov.b64 %0,{%1,%2};" : "=l"(r) : "f"(a), "f"(b)); return r;
}
__device__ __forceinline__ void fma2(u64& acc, u64 a, u64 w) {
    asm("fma.rn.f32x2 %0,%1,%2,%3;" : "=l"(acc) : "l"(a), "l"(w), "l"(acc));
}
__device__ __forceinline__ float2 unpack2(u64 v) {
    float2 f; asm("mov.b64 {%0,%1},%2;" : "=f"(f.x), "=f"(f.y) : "l"(v)); return f;
}

// ---------------- setup: pack all weights once (fragment order, fp16) ----------------
__global__ void packw_kernel(const float* __restrict__ Wtxn,
                             const float* __restrict__ convW) {
    int m = blockIdx.x;
    const float* W = (m == 0) ? Wtxn : convW + (size_t)(m - 1) * 4096;
    int t = threadIdx.x;
    for (int i = t; i < 1024; i += 256) {
        int kk = i >> 8, nt = (i >> 5) & 7, ln = i & 31;
        int col = nt * 8 + (ln >> 2);
        int k0 = kk * 16 + 2 * (ln & 3);
        __half2 lo = __floats2half2_rn(W[k0 * 64 + col], W[(k0 + 1) * 64 + col]);
        __half2 hi = __floats2half2_rn(W[(k0 + 8) * 64 + col], W[(k0 + 9) * 64 + col]);
        g_wpk[m][i * 2]     = *(u32*)&lo;
        g_wpk[m][i * 2 + 1] = *(u32*)&hi;
    }
}

// ---------------- setup: counts ----------------
__global__ void zero_cnt_kernel() {
    int i = blockIdx.x * blockDim.x + threadIdx.x;
    if (i < NUc) { g_c_u2u[i] = 0; g_c_u2t_s[i] = 0; g_c_t2u_d[i] = 0; }
    if (i < NTc) { g_c_t2t[i] = 0; g_c_u2t_d[i] = 0; g_c_t2u_s[i] = 0; }
    if (i < 128) g_colsum[i] = 0.f;
}

__global__ void count_kernel(const int* __restrict__ eu2u, const int* __restrict__ et2t,
                             const int* __restrict__ eu2t, const int* __restrict__ et2u) {
    int e = blockIdx.x * blockDim.x + threadIdx.x;
    if (e >= Ec) return;
    atomicAdd(&g_c_u2u[eu2u[Ec + e]], 1);
    atomicAdd(&g_c_t2t[et2t[Ec + e]], 1);
    atomicAdd(&g_c_u2t_d[eu2t[Ec + e]], 1);
    atomicAdd(&g_c_u2t_s[eu2t[e]],      1);
    atomicAdd(&g_c_t2u_d[et2u[Ec + e]], 1);
    atomicAdd(&g_c_t2u_s[et2u[e]],      1);
}

// ---------------- setup: 4 exclusive scans (one block each) ----------------
__global__ void scan4_kernel() {
    const int* cnt; int* off; int* cur; int n;
    switch (blockIdx.x) {
        case 0:  cnt = g_c_u2u;   off = g_off_u2u; cur = g_cur_u2u; n = NUc; break;
        case 1:  cnt = g_c_t2t;   off = g_off_t2t; cur = g_cur_t2t; n = NTc; break;
        case 2:  cnt = g_c_u2t_d; off = g_off_u2t; cur = g_cur_u2t; n = NTc; break;
        default: cnt = g_c_t2u_d; off = g_off_t2u; cur = g_cur_t2u; n = NUc; break;
    }
    __shared__ int sh[1024];
    int tid = threadIdx.x;
    int chunk = (n + 1023) >> 10;
    int start = tid * chunk;
    int end = min(start + chunk, n);
    int s = 0;
    for (int i = start; i < end; i++) s += cnt[i];
    sh[tid] = s;
    __syncthreads();
    for (int d = 1; d < 1024; d <<= 1) {
        int v = (tid >= d) ? sh[tid - d] : 0;
        __syncthreads();
        sh[tid] += v;
        __syncthreads();
    }
    int run = sh[tid] - s;
    for (int i = start; i < end; i++) { off[i] = run; cur[i] = run; run += cnt[i]; }
    if (start < n && end == n) off[n] = run;
}

// ---------------- setup: CSR fill ----------------
__global__ void fill_kernel(const int* __restrict__ eu2u, const int* __restrict__ et2t,
                            const int* __restrict__ eu2t, const int* __restrict__ et2u) {
    int e = blockIdx.x * blockDim.x + threadIdx.x;
    if (e >= Ec) return;
    int p;
    p = atomicAdd(&g_cur_u2u[eu2u[Ec + e]], 1); g_csr_u2u[p] = eu2u[e];
    p = atomicAdd(&g_cur_t2t[et2t[Ec + e]], 1); g_csr_t2t[p] = et2t[e];
    p = atomicAdd(&g_cur_u2t[eu2t[Ec + e]], 1); g_csr_u2t[p] = eu2t[e];
    p = atomicAdd(&g_cur_t2u[et2u[Ec + e]], 1); g_csr_t2u[p] = et2u[e];
}

__global__ void dinv_kernel() {
    int i = blockIdx.x * blockDim.x + threadIdx.x;
    if (i < NUc) {
        g_d_u2u[i] = rsqrtf((float)g_c_u2u[i] + 1.f);
        int cs = g_c_u2t_s[i]; g_ds_u2t[i] = (cs > 0) ? rsqrtf((float)cs) : 0.f;
        int cd = g_c_t2u_d[i]; g_dd_t2u[i] = (cd > 0) ? rsqrtf((float)cd) : 0.f;
    }
    if (i < NTc) {
        g_d_t2t[i] = rsqrtf((float)g_c_t2t[i] + 1.f);
        int cd = g_c_u2t_d[i]; g_dd_u2t[i] = (cd > 0) ? rsqrtf((float)cd) : 0.f;
        int cs = g_c_t2u_s[i]; g_ds_t2u[i] = (cs > 0) ? rsqrtf((float)cs) : 0.f;
    }
}

// ---------------- DUAL transform: 512 threads, split warp-groups ----------------
// warps 0-7 compute A@W0 (scaled sc0 -> O0), warps 8-15 compute A@W1 (sc1 -> O1).
// Shared A tile (128x32 u32 fp16, pitch 36); per-group weight smem; one staging pass.
__device__ __forceinline__ void dual512_gemm(const u32* __restrict__ Ah,
                                             const u32* __restrict__ Wp0,
                                             const u32* __restrict__ Wp1,
                                             const float* __restrict__ sc0,
                                             const float* __restrict__ sc1,
                                             u32* __restrict__ O0h,
                                             u32* __restrict__ O1h,
                                             int N, int tile) {
    extern __shared__ u32 smu[];
    u32* Wf0 = smu;             // 2048 u32
    u32* Wf1 = smu + 2048;      // 2048 u32
    u32* As  = smu + 4096;      // 128*36 u32; reused as staging
    int t = threadIdx.x;
    int lane = t & 31, wid = t >> 5;
    int wg = wid >> 3, wl = wid & 7;
    int fr = lane >> 2, fc = lane & 3;
    int row0 = tile * 128;

    // cooperative loads: weights (1 uint4 each matrix per thread) + A tile
    ((uint4*)Wf0)[t] = ((const uint4*)Wp0)[t];
    ((uint4*)Wf1)[t] = ((const uint4*)Wp1)[t];
    for (int i = t; i < 128 * 32; i += 512) {
        int r = i >> 5, c = i & 31;
        int gr = row0 + r;
        As[r * 36 + c] = (gr < N) ? Ah[((size_t)gr << 5) + c] : 0u;
    }
    __syncthreads();

    const u32* Wf = wg ? Wf1 : Wf0;
    int rbase = wl * 16;
    float acc[8][4];
#pragma unroll
    for (int nt = 0; nt < 8; nt++)
#pragma unroll
        for (int j = 0; j < 4; j++) acc[nt][j] = 0.f;

#pragma unroll
    for (int kk = 0; kk < 4; kk++) {
        int abase = (rbase + fr) * 36 + kk * 8 + fc;
        u32 a0 = As[abase];
        u32 a1 = As[abase + 8 * 36];
        u32 a2 = As[abase + 4];
        u32 a3 = As[abase + 8 * 36 + 4];
#pragma unroll
        for (int nt = 0; nt < 8; nt++) {
            uint2 b = *(const uint2*)&Wf[(size_t)(((kk << 3) + nt) << 5 | lane) * 2];
            mma_f16(acc[nt], a0, a1, a2, a3, b.x, b.y);
        }
    }

    // epilogue: both groups stage fp8 side-by-side in one pass
    int gr0 = row0 + rbase + fr, gr1 = gr0 + 8;
    const float* sc = wg ? sc1 : sc0;
    float s0 = sc[min(gr0, N - 1)], s1 = sc[min(gr1, N - 1)];
    __syncthreads();
    u16* st16 = (u16*)As;   // row pitch 72 u16; group0 cols 0..31, group1 cols 32..63
    int cb = wg * 32;
#pragma unroll
    for (int nt = 0; nt < 8; nt++) {
        st16[(rbase + fr) * 72 + cb + nt * 4 + fc] =
            pack2_e4m3(acc[nt][0] * s0, acc[nt][1] * s0);
        st16[(rbase + fr + 8) * 72 + cb + nt * 4 + fc] =
            pack2_e4m3(acc[nt][2] * s1, acc[nt][3] * s1);
    }
    __syncthreads();
    for (int i = t; i < 1024; i += 512) {
        int o = i >> 9, rem = i & 511;
        int r = rem >> 2, q = (rem & 3) << 2;
        int gr = row0 + r;
        if (gr < N) {
            u32* O = o ? O1h : O0h;
            *(uint4*)&O[((size_t)gr << 4) + q] = *(uint4*)&As[r * 36 + o * 16 + q];
        }
    }
}

#define GU_T ((NUc + 127) / 128)
#define GT_T ((NTc + 127) / 128)

__global__ void __launch_bounds__(512) transform_kernel(int l) {
    int b = blockIdx.x;
    int m = 1 + l * 4;
    if (b < GU_T) {
        dual512_gemm(g_huh, g_wpk[m + 0], g_wpk[m + 2], g_d_u2u, g_ds_u2t,
                     g_mu0h, g_mu1h, NUc, b);
    } else {
        dual512_gemm(g_hth, g_wpk[m + 1], g_wpk[m + 3], g_d_t2t, g_ds_t2u,
                     g_mt0h, g_mt1h, NTc, b - GU_T);
    }
}

// ---------------- embed_txn: fp16 MMA, 256 threads (single output) ----------------
__global__ void __launch_bounds__(256) embed_txn_kernel(const float* __restrict__ x,
                                                        const float* __restrict__ bias) {
    extern __shared__ u32 smu[];
    u32* Wf = smu;             // 2048 u32
    u32* As = smu + 2048;      // 128*36 u32
    int t = threadIdx.x;
    int lane = t & 31, wid = t >> 5;
    int fr = lane >> 2, fc = lane & 3;
    int row0 = blockIdx.x * 128;
    const int N = NTc;

    for (int i = t; i < 512; i += 256) ((uint4*)Wf)[i] = ((const uint4*)g_wpk[0])[i];
    for (int i = t; i < 128 * 32; i += 256) {
        int r = i >> 5, c = i & 31;
        int gr = row0 + r;
        u32 v = 0;
        if (gr < N) {
            const float2 f = *(const float2*)&x[((size_t)gr << 6) + 2 * c];
            __half2 h = __floats2half2_rn(f.x, f.y);
            v = *(u32*)&h;
        }
        As[r * 36 + c] = v;
    }
    __syncthreads();

    int rbase = wid * 16;
    float acc[8][4];
#pragma unroll
    for (int nt = 0; nt < 8; nt++)
#pragma unroll
        for (int j = 0; j < 4; j++) acc[nt][j] = 0.f;
#pragma unroll
    for (int kk = 0; kk < 4; kk++) {
        int abase = (rbase + fr) * 36 + kk * 8 + fc;
        u32 a0 = As[abase];
        u32 a1 = As[abase + 8 * 36];
        u32 a2 = As[abase + 4];
        u32 a3 = As[abase + 8 * 36 + 4];
#pragma unroll
        for (int nt = 0; nt < 8; nt++) {
            uint2 b = *(const uint2*)&Wf[(size_t)(((kk << 3) + nt) << 5 | lane) * 2];
            mma_f16(acc[nt], a0, a1, a2, a3, b.x, b.y);
        }
    }
    __syncthreads();
#pragma unroll
    for (int nt = 0; nt < 8; nt++) {
        float bx = bias[nt * 8 + 2 * fc], by = bias[nt * 8 + 2 * fc + 1];
        __half2 h0 = __floats2half2_rn(acc[nt][0] + bx, acc[nt][1] + by);
        __half2 h1 = __floats2half2_rn(acc[nt][2] + bx, acc[nt][3] + by);
        As[(rbase + fr) * 36 + nt * 4 + fc]     = *(u32*)&h0;
        As[(rbase + fr + 8) * 36 + nt * 4 + fc] = *(u32*)&h1;
    }
    __syncthreads();
    for (int i = t; i < 128 * 8; i += 256) {
        int r = i >> 3, q = (i & 7) << 2;
        int gr = row0 + r;
        if (gr < N) *(uint4*)&g_hth[((size_t)gr << 5) + q] = *(uint4*)&As[r * 36 + q];
    }
}

// ---------------- f32x2 embed for K=32 ----------------
__global__ void __launch_bounds__(256) embed_user_kernel(const float* __restrict__ A,
                                                         const float* __restrict__ W,
                                                         const float* __restrict__ b) {
    const int K = 32;
    __shared__ float Ws[K * 64];
    __shared__ float As[128 * (K + 1)];
    int t = threadIdx.x;
    for (int i = t; i < K * 64; i += 256) Ws[i] = W[i];
    int row0 = blockIdx.x * 128;
    for (int i = t; i < 128 * K; i += 256) {
        int r = i / K, c = i & (K - 1);
        int gr = row0 + r;
        As[r * (K + 1) + c] = (gr < NUc) ? A[(size_t)gr * K + c] : 0.f;
    }
    __syncthreads();
    int cg = t & 7, r0 = (t >> 3) << 2;
    u64 binit[4];
#pragma unroll
    for (int j = 0; j < 4; j++)
        binit[j] = pack2ab(b[(cg << 3) + (j << 1)], b[(cg << 3) + (j << 1) + 1]);
    u64 acc[4][4];
#pragma unroll
    for (int rr = 0; rr < 4; rr++)
#pragma unroll
        for (int j = 0; j < 4; j++) acc[rr][j] = binit[j];
#pragma unroll 4
    for (int k = 0; k < K; k++) {
        const float* wp = &Ws[(k << 6) + (cg << 3)];
        ulonglong2 wa = *(const ulonglong2*)wp;
        ulonglong2 wb = *(const ulonglong2*)(wp + 4);
#pragma unroll
        for (int rr = 0; rr < 4; rr++) {
            u64 a2 = pack2(As[(r0 + rr) * (K + 1) + k]);
            fma2(acc[rr][0], a2, wa.x);
            fma2(acc[rr][1], a2, wa.y);
            fma2(acc[rr][2], a2, wb.x);
            fma2(acc[rr][3], a2, wb.y);
        }
    }
#pragma unroll
    for (int rr = 0; rr < 4; rr++) {
        int gr = row0 + r0 + rr;
        if (gr < NUc) {
            float2 p0 = unpack2(acc[rr][0]), p1 = unpack2(acc[rr][1]);
            float2 p2 = unpack2(acc[rr][2]), p3 = unpack2(acc[rr][3]);
            __half2 h0 = __floats2half2_rn(p0.x, p0.y);
            __half2 h1 = __floats2half2_rn(p1.x, p1.y);
            __half2 h2 = __floats2half2_rn(p2.x, p2.y);
            __half2 h3 = __floats2half2_rn(p3.x, p3.y);
            uint4 pk;
            pk.x = *(u32*)&h0; pk.y = *(u32*)&h1; pk.z = *(u32*)&h2; pk.w = *(u32*)&h3;
            *(uint4*)&g_huh[((size_t)gr << 5) + (cg << 2)] = pk;
        }
    }
}

// ---------------- fused gather-aggregate + bias + relu (fp8 messages) ----------------
__device__ __forceinline__ void gather_loop(float* acc, const u32* __restrict__ m,
                                            const int* __restrict__ csr,
                                            int e, int end, int woff) {
    while (e < end && (e & 3)) {
        int s = __ldg(csr + e);
        acc_h8(acc, fp8_widen8(__ldg((const uint2*)(m + ((size_t)s << 4) + woff))));
        e++;
    }
    for (; e + 4 <= end; e += 4) {
        int4 s = __ldg((const int4*)(csr + e));
        uint2 v0 = __ldg((const uint2*)(m + ((size_t)s.x << 4) + woff));
        uint2 v1 = __ldg((const uint2*)(m + ((size_t)s.y << 4) + woff));
        uint2 v2 = __ldg((const uint2*)(m + ((size_t)s.z << 4) + woff));
        uint2 v3 = __ldg((const uint2*)(m + ((size_t)s.w << 4) + woff));
        uint4 x0 = fp8_widen8(v0), x1 = fp8_widen8(v1);
        uint4 x2 = fp8_widen8(v2), x3 = fp8_widen8(v3);
        uint4 tt = h2add4(h2add4(x0, x1), h2add4(x2, x3));
        acc_h8(acc, tt);
    }
    for (; e < end; e++) {
        int s = __ldg(csr + e);
        acc_h8(acc, fp8_widen8(__ldg((const uint2*)(m + ((size_t)s << 4) + woff))));
    }
}

__device__ __forceinline__ void agg_body(int idx,
                                         const u32* __restrict__ mA,
                                         const int* __restrict__ offA,
                                         const int* __restrict__ csrA,
                                         const float* __restrict__ dA,
                                         const u32* __restrict__ mB,
                                         const int* __restrict__ offB,
                                         const int* __restrict__ csrB,
                                         const float* __restrict__ dB,
                                         const float* __restrict__ bA,
                                         const float* __restrict__ bB,
                                         u32* __restrict__ Outh, int N) {
    int g = idx >> 3;
    if (g >= N) return;
    int q = idx & 7;
    int woff = q << 1;
    float a[8], b[8];
#pragma unroll
    for (int i = 0; i < 8; i++) { a[i] = 0.f; b[i] = 0.f; }
    acc_h8(a, fp8_widen8(__ldg((const uint2*)(mA + ((size_t)g << 4) + woff))));
    gather_loop(a, mA, csrA, offA[g], offA[g + 1], woff);
    gather_loop(b, mB, csrB, offB[g], offB[g + 1], woff);
    float da = dA[g], db = dB[g];
    int c0 = q << 3;
    float4 bAv0 = __ldg((const float4*)(bA + c0)), bAv1 = __ldg((const float4*)(bA + c0 + 4));
    float4 bBv0 = __ldg((const float4*)(bB + c0)), bBv1 = __ldg((const float4*)(bB + c0 + 4));
    float o0 = fmaxf(0.5f * (da * a[0] + db * b[0] + bAv0.x + bBv0.x), 0.f);
    float o1 = fmaxf(0.5f * (da * a[1] + db * b[1] + bAv0.y + bBv0.y), 0.f);
    float o2 = fmaxf(0.5f * (da * a[2] + db * b[2] + bAv0.z + bBv0.z), 0.f);
    float o3 = fmaxf(0.5f * (da * a[3] + db * b[3] + bAv0.w + bBv0.w), 0.f);
    float o4 = fmaxf(0.5f * (da * a[4] + db * b[4] + bAv1.x + bBv1.x), 0.f);
    float o5 = fmaxf(0.5f * (da * a[5] + db * b[5] + bAv1.y + bBv1.y), 0.f);
    float o6 = fmaxf(0.5f * (da * a[6] + db * b[6] + bAv1.z + bBv1.z), 0.f);
    float o7 = fmaxf(0.5f * (da * a[7] + db * b[7] + bAv1.w + bBv1.w), 0.f);
    __half2 h0 = __floats2half2_rn(o0, o1);
    __half2 h1 = __floats2half2_rn(o2, o3);
    __half2 h2 = __floats2half2_rn(o4, o5);
    __half2 h3 = __floats2half2_rn(o6, o7);
    uint4 pk;
    pk.x = *(u32*)&h0; pk.y = *(u32*)&h1; pk.z = *(u32*)&h2; pk.w = *(u32*)&h3;
    *(uint4*)&Outh[((size_t)g << 5) + (q << 2)] = pk;
}

#define AU_B ((NUc * 8 + 255) / 256)
#define AT_B ((NTc * 8 + 255) / 256)

__global__ void __launch_bounds__(256) agg_kernel(const float* __restrict__ B) {
    int b = blockIdx.x;
    if (b < AU_B) {
        agg_body(b * 256 + threadIdx.x,
                 g_mu0h, g_off_u2u, g_csr_u2u, g_d_u2u,
                 g_mt1h, g_off_t2u, g_csr_t2u, g_dd_t2u,
                 B + 0 * 64, B + 3 * 64, g_huh, NUc);
    } else {
        agg_body((b - AU_B) * 256 + threadIdx.x,
                 g_mt0h, g_off_t2t, g_csr_t2t, g_d_t2t,
                 g_mu1h, g_off_u2t, g_csr_u2t, g_dd_u2t,
                 B + 1 * 64, B + 2 * 64, g_hth, NTc);
    }
}

// ---------------- readout (fp16 h) ----------------
#define CS_BLOCKS 296
__global__ void colsum_kernel() {
    int b = blockIdx.x;
    if (b < CS_BLOCKS) {
        int t = b * blockDim.x + threadIdx.x;
        float s0 = 0.f, s1 = 0.f;
        const int n = NUc * 32;
        for (int i = t; i < n; i += CS_BLOCKS * 256) {
            u32 v = g_huh[i];
            float2 f = __half22float2(*(__half2*)&v);
            s0 += f.x; s1 += f.y;
        }
        int j = (t & 31) << 1;
        atomicAdd(&g_colsum[j], s0);
        atomicAdd(&g_colsum[j + 1], s1);
    } else {
        int t = (b - CS_BLOCKS) * blockDim.x + threadIdx.x;
        float s0 = 0.f, s1 = 0.f;
        const int n = NTc * 32;
        for (int i = t; i < n; i += CS_BLOCKS * 256) {
            u32 v = g_hth[i];
            float2 f = __half22float2(*(__half2*)&v);
            s0 += f.x; s1 += f.y;
        }
        int j = (t & 31) << 1;
        atomicAdd(&g_colsum[64 + j], s0);
        atomicAdd(&g_colsum[64 + j + 1], s1);
    }
}

__global__ void mlp_kernel(const float* __restrict__ W1, const float* __restrict__ b1,
                           const float* __restrict__ W2, const float* __restrict__ b2,
                           float* __restrict__ out) {
    __shared__ float x[64];
    __shared__ float y[64];
    int t = threadIdx.x;
    x[t] = 0.5f * (g_colsum[t] * (1.f / NUc) + g_colsum[64 + t] * (1.f / NTc));
    __syncthreads();
    float s = b1[t];
    for (int k = 0; k < 64; k++) s += x[k] * W1[k * 64 + t];
    y[t] = fmaxf(s, 0.f) * W2[t];
    __syncthreads();
    if (t == 0) {
        float o = b2[0];
        for (int j = 0; j < 64; j++) o += y[j];
        out[0] = 1.f / (1.f + expf(-o));
    }
}

// ---------------- launch ----------------
extern "C" void kernel_launch(void* const* d_in, const int* in_sizes, int n_in,
                              void* d_out, int out_size) {
    const float* x_user     = (const float*)d_in[0];
    const float* x_txn      = (const float*)d_in[1];
    const int*   ei_u2u     = (const int*)d_in[2];
    const int*   ei_t2t     = (const int*)d_in[3];
    const int*   ei_u2t     = (const int*)d_in[4];
    const int*   ei_t2u     = (const int*)d_in[5];
    const float* W_emb_user = (const float*)d_in[6];
    const float* b_emb_user = (const float*)d_in[7];
    const float* W_emb_txn  = (const float*)d_in[8];
    const float* b_emb_txn  = (const float*)d_in[9];
    const float* conv_W     = (const float*)d_in[10];
    const float* conv_b     = (const float*)d_in[11];
    const float* W1         = (const float*)d_in[12];
    const float* b1         = (const float*)d_in[13];
    const float* W2         = (const float*)d_in[14];
    const float* b2         = (const float*)d_in[15];
    float* out = (float*)d_out;

    const int SMEM_DUAL = (4096 + 128 * 36) * 4;   // 34816
    const int SMEM_SNGL = (2048 + 128 * 36) * 4;   // 26624

    packw_kernel<<<13, 256>>>(W_emb_txn, conv_W);
    zero_cnt_kernel<<<(NTc + 255) / 256, 256>>>();
    count_kernel<<<(Ec + 255) / 256, 256>>>(ei_u2u, ei_t2t, ei_u2t, ei_t2u);
    embed_txn_kernel<<<GT_T, 256, SMEM_SNGL>>>(x_txn, b_emb_txn);
    embed_user_kernel<<<(NUc + 127) / 128, 256>>>(x_user, W_emb_user, b_emb_user);
    scan4_kernel<<<4, 1024>>>();
    fill_kernel<<<(Ec + 255) / 256, 256>>>(ei_u2u, ei_t2t, ei_u2t, ei_t2u);
    dinv_kernel<<<(NTc + 255) / 256, 256>>>();

    // ---- layers ----
    for (int l = 0; l < 3; l++) {
        const float* B = conv_b + (size_t)l * 4 * 64;
        transform_kernel<<<GU_T + GT_T, 512, SMEM_DUAL>>>(l);
        agg_kernel<<<AU_B + AT_B, 256>>>(B);
    }

    // ---- readout ----
    colsum_kernel<<<2 * CS_BLOCKS, 256>>>();
    mlp_kernel<<<1, 64>>>(W1, b1, W2, b2, out);
}

// round 16
// speedup vs baseline: 1.0394x; 1.0067x over previous
#include <cuda_runtime.h>
#include <cuda_fp16.h>
#include <cuda_fp8.h>
#include <cstdint>
#include <cstddef>

#define NUc 100000
#define NTc 200000
#define Ec  1000000

typedef unsigned long long u64;
typedef unsigned int u32;
typedef unsigned short u16;

// ---------------- scratch (device globals; no allocation) ----------------
__device__ __align__(128) u32 g_huh[NUc*32];
__device__ __align__(128) u32 g_hth[NTc*32];
__device__ __align__(128) u32 g_mu0h[NUc*16];
__device__ __align__(128) u32 g_mu1h[NUc*16];
__device__ __align__(128) u32 g_mt0h[NTc*16];
__device__ __align__(128) u32 g_mt1h[NTc*16];

__device__ __align__(128) u32 g_wpk[13][2048];

__device__ int g_c_u2u[NUc];
__device__ int g_c_t2t[NTc];
__device__ int g_c_u2t_d[NTc];
__device__ int g_c_t2u_d[NUc];
__device__ int g_c_u2t_s[NUc];
__device__ int g_c_t2u_s[NTc];

__device__ float g_d_u2u[NUc];
__device__ float g_d_t2t[NTc];
__device__ float g_ds_u2t[NUc];
__device__ float g_dd_u2t[NTc];
__device__ float g_ds_t2u[NTc];
__device__ float g_dd_t2u[NUc];

__device__ int g_off_u2u[NUc+1];
__device__ int g_off_t2t[NTc+1];
__device__ int g_off_u2t[NTc+1];
__device__ int g_off_t2u[NUc+1];
__device__ int g_cur_u2u[NUc];
__device__ int g_cur_t2t[NTc];
__device__ int g_cur_u2t[NTc];
__device__ int g_cur_t2u[NUc];
__device__ int g_csr_u2u[Ec];
__device__ int g_csr_t2t[Ec];
__device__ int g_csr_u2t[Ec];
__device__ int g_csr_t2u[Ec];

__device__ float g_colsum[128];

// ---------------- helpers ----------------
__device__ __forceinline__ void mma_f16(float* c, u32 a0, u32 a1, u32 a2, u32 a3,
                                        u32 b0, u32 b1) {
    asm volatile(
        "mma.sync.aligned.m16n8k16.row.col.f32.f16.f16.f32 "
        "{%0,%1,%2,%3}, {%4,%5,%6,%7}, {%8,%9}, {%0,%1,%2,%3};"
        : "+f"(c[0]), "+f"(c[1]), "+f"(c[2]), "+f"(c[3])
        : "r"(a0), "r"(a1), "r"(a2), "r"(a3), "r"(b0), "r"(b1));
}
__device__ __forceinline__ void acc_h8(float* acc, uint4 v) {
    float2 f;
    f = __half22float2(*(__half2*)&v.x); acc[0] += f.x; acc[1] += f.y;
    f = __half22float2(*(__half2*)&v.y); acc[2] += f.x; acc[3] += f.y;
    f = __half22float2(*(__half2*)&v.z); acc[4] += f.x; acc[5] += f.y;
    f = __half22float2(*(__half2*)&v.w); acc[6] += f.x; acc[7] += f.y;
}
__device__ __forceinline__ uint4 h2add4(uint4 a, uint4 b) {
    uint4 r;
    *(__half2*)&r.x = __hadd2(*(__half2*)&a.x, *(__half2*)&b.x);
    *(__half2*)&r.y = __hadd2(*(__half2*)&a.y, *(__half2*)&b.y);
    *(__half2*)&r.z = __hadd2(*(__half2*)&a.z, *(__half2*)&b.z);
    *(__half2*)&r.w = __hadd2(*(__half2*)&a.w, *(__half2*)&b.w);
    return r;
}
__device__ __forceinline__ u16 pack2_e4m3(float c0, float c1) {
    return __nv_cvt_float2_to_fp8x2(make_float2(c0, c1), __NV_SATFINITE, __NV_E4M3);
}
__device__ __forceinline__ u32 fp8x2_to_h2(u16 v) {
    __half2_raw r = __nv_cvt_fp8x2_to_halfraw2(v, __NV_E4M3);
    return *(u32*)&r;
}
__device__ __forceinline__ uint4 fp8_widen8(uint2 v) {
    uint4 r;
    r.x = fp8x2_to_h2((u16)(v.x & 0xffff));
    r.y = fp8x2_to_h2((u16)(v.x >> 16));
    r.z = fp8x2_to_h2((u16)(v.y & 0xffff));
    r.w = fp8x2_to_h2((u16)(v.y >> 16));
    return r;
}
__device__ __forceinline__ u64 pack2(float a) {
    u64 r; asm("mov.b64 %0,{%1,%1};" : "=l"(r) : "f"(a)); return r;
}
__device__ __forceinline__ u64 pack2ab(float a, float b) {
    u64 r; asm("mov.b64 %0,{%1,%2};" : "=l"(r) : "f"(a), "f"(b)); return r;
}
__device__ __forceinline__ void fma2(u64& acc, u64 a, u64 w) {
    asm("fma.rn.f32x2 %0,%1,%2,%3;" : "=l"(acc) : "l"(a), "l"(w), "l"(acc));
}
__device__ __forceinline__ float2 unpack2(u64 v) {
    float2 f; asm("mov.b64 {%0,%1},%2;" : "=f"(f.x), "=f"(f.y) : "l"(v)); return f;
}

// ---------------- setup: pack all weights once (fragment order, fp16) ----------------
__global__ void packw_kernel(const float* __restrict__ Wtxn,
                             const float* __restrict__ convW) {
    int m = blockIdx.x;
    const float* W = (m == 0) ? Wtxn : convW + (size_t)(m - 1) * 4096;
    int t = threadIdx.x;
    for (int i = t; i < 1024; i += 256) {
        int kk = i >> 8, nt = (i >> 5) & 7, ln = i & 31;
        int col = nt * 8 + (ln >> 2);
        int k0 = kk * 16 + 2 * (ln & 3);
        __half2 lo = __floats2half2_rn(W[k0 * 64 + col], W[(k0 + 1) * 64 + col]);
        __half2 hi = __floats2half2_rn(W[(k0 + 8) * 64 + col], W[(k0 + 9) * 64 + col]);
        g_wpk[m][i * 2]     = *(u32*)&lo;
        g_wpk[m][i * 2 + 1] = *(u32*)&hi;
    }
}

// ---------------- setup: counts ----------------
__global__ void zero_cnt_kernel() {
    int i = blockIdx.x * blockDim.x + threadIdx.x;
    if (i < NUc) { g_c_u2u[i] = 0; g_c_u2t_s[i] = 0; g_c_t2u_d[i] = 0; }
    if (i < NTc) { g_c_t2t[i] = 0; g_c_u2t_d[i] = 0; g_c_t2u_s[i] = 0; }
    if (i < 128) g_colsum[i] = 0.f;
}

__global__ void count_kernel(const int* __restrict__ eu2u, const int* __restrict__ et2t,
                             const int* __restrict__ eu2t, const int* __restrict__ et2u) {
    int e = blockIdx.x * blockDim.x + threadIdx.x;
    if (e >= Ec) return;
    atomicAdd(&g_c_u2u[eu2u[Ec + e]], 1);
    atomicAdd(&g_c_t2t[et2t[Ec + e]], 1);
    atomicAdd(&g_c_u2t_d[eu2t[Ec + e]], 1);
    atomicAdd(&g_c_u2t_s[eu2t[e]],      1);
    atomicAdd(&g_c_t2u_d[et2u[Ec + e]], 1);
    atomicAdd(&g_c_t2u_s[et2u[e]],      1);
}

// ---------------- setup: 4 exclusive scans (one block each) ----------------
__global__ void scan4_kernel() {
    const int* cnt; int* off; int* cur; int n;
    switch (blockIdx.x) {
        case 0:  cnt = g_c_u2u;   off = g_off_u2u; cur = g_cur_u2u; n = NUc; break;
        case 1:  cnt = g_c_t2t;   off = g_off_t2t; cur = g_cur_t2t; n = NTc; break;
        case 2:  cnt = g_c_u2t_d; off = g_off_u2t; cur = g_cur_u2t; n = NTc; break;
        default: cnt = g_c_t2u_d; off = g_off_t2u; cur = g_cur_t2u; n = NUc; break;
    }
    __shared__ int sh[1024];
    int tid = threadIdx.x;
    int chunk = (n + 1023) >> 10;
    int start = tid * chunk;
    int end = min(start + chunk, n);
    int s = 0;
    for (int i = start; i < end; i++) s += cnt[i];
    sh[tid] = s;
    __syncthreads();
    for (int d = 1; d < 1024; d <<= 1) {
        int v = (tid >= d) ? sh[tid - d] : 0;
        __syncthreads();
        sh[tid] += v;
        __syncthreads();
    }
    int run = sh[tid] - s;
    for (int i = start; i < end; i++) { off[i] = run; cur[i] = run; run += cnt[i]; }
    if (start < n && end == n) off[n] = run;
}

// ---------------- setup: CSR fill ----------------
__global__ void fill_kernel(const int* __restrict__ eu2u, const int* __restrict__ et2t,
                            const int* __restrict__ eu2t, const int* __restrict__ et2u) {
    int e = blockIdx.x * blockDim.x + threadIdx.x;
    if (e >= Ec) return;
    int p;
    p = atomicAdd(&g_cur_u2u[eu2u[Ec + e]], 1); g_csr_u2u[p] = eu2u[e];
    p = atomicAdd(&g_cur_t2t[et2t[Ec + e]], 1); g_csr_t2t[p] = et2t[e];
    p = atomicAdd(&g_cur_u2t[eu2t[Ec + e]], 1); g_csr_u2t[p] = eu2t[e];
    p = atomicAdd(&g_cur_t2u[et2u[Ec + e]], 1); g_csr_t2u[p] = et2u[e];
}

__global__ void dinv_kernel() {
    int i = blockIdx.x * blockDim.x + threadIdx.x;
    if (i < NUc) {
        g_d_u2u[i] = rsqrtf((float)g_c_u2u[i] + 1.f);
        int cs = g_c_u2t_s[i]; g_ds_u2t[i] = (cs > 0) ? rsqrtf((float)cs) : 0.f;
        int cd = g_c_t2u_d[i]; g_dd_t2u[i] = (cd > 0) ? rsqrtf((float)cd) : 0.f;
    }
    if (i < NTc) {
        g_d_t2t[i] = rsqrtf((float)g_c_t2t[i] + 1.f);
        int cd = g_c_u2t_d[i]; g_dd_u2t[i] = (cd > 0) ? rsqrtf((float)cd) : 0.f;
        int cs = g_c_t2u_s[i]; g_ds_t2u[i] = (cs > 0) ? rsqrtf((float)cs) : 0.f;
    }
}

// ---------------- DUAL transform: 512 threads, split warp-groups ----------------
// warps 0-7 compute A@W0 (scaled sc0 -> O0), warps 8-15 compute A@W1 (sc1 -> O1).
// Shared A tile (128x32 u32 fp16, pitch 36); per-group weight smem; one staging pass.
__device__ __forceinline__ void dual512_gemm(const u32* __restrict__ Ah,
                                             const u32* __restrict__ Wp0,
                                             const u32* __restrict__ Wp1,
                                             const float* __restrict__ sc0,
                                             const float* __restrict__ sc1,
                                             u32* __restrict__ O0h,
                                             u32* __restrict__ O1h,
                                             int N, int tile) {
    extern __shared__ u32 smu[];
    u32* Wf0 = smu;             // 2048 u32
    u32* Wf1 = smu + 2048;      // 2048 u32
    u32* As  = smu + 4096;      // 128*36 u32; reused as staging
    int t = threadIdx.x;
    int lane = t & 31, wid = t >> 5;
    int wg = wid >> 3, wl = wid & 7;
    int fr = lane >> 2, fc = lane & 3;
    int row0 = tile * 128;

    // cooperative loads: weights (1 uint4 each matrix per thread) + A tile
    ((uint4*)Wf0)[t] = ((const uint4*)Wp0)[t];
    ((uint4*)Wf1)[t] = ((const uint4*)Wp1)[t];
    for (int i = t; i < 128 * 32; i += 512) {
        int r = i >> 5, c = i & 31;
        int gr = row0 + r;
        As[r * 36 + c] = (gr < N) ? Ah[((size_t)gr << 5) + c] : 0u;
    }
    __syncthreads();

    const u32* Wf = wg ? Wf1 : Wf0;
    int rbase = wl * 16;
    float acc[8][4];
#pragma unroll
    for (int nt = 0; nt < 8; nt++)
#pragma unroll
        for (int j = 0; j < 4; j++) acc[nt][j] = 0.f;

#pragma unroll
    for (int kk = 0; kk < 4; kk++) {
        int abase = (rbase + fr) * 36 + kk * 8 + fc;
        u32 a0 = As[abase];
        u32 a1 = As[abase + 8 * 36];
        u32 a2 = As[abase + 4];
        u32 a3 = As[abase + 8 * 36 + 4];
#pragma unroll
        for (int nt = 0; nt < 8; nt++) {
            uint2 b = *(const uint2*)&Wf[(size_t)(((kk << 3) + nt) << 5 | lane) * 2];
            mma_f16(acc[nt], a0, a1, a2, a3, b.x, b.y);
        }
    }

    // epilogue: both groups stage fp8 side-by-side in one pass
    int gr0 = row0 + rbase + fr, gr1 = gr0 + 8;
    const float* sc = wg ? sc1 : sc0;
    float s0 = sc[min(gr0, N - 1)], s1 = sc[min(gr1, N - 1)];
    __syncthreads();
    u16* st16 = (u16*)As;   // row pitch 72 u16; group0 cols 0..31, group1 cols 32..63
    int cb = wg * 32;
#pragma unroll
    for (int nt = 0; nt < 8; nt++) {
        st16[(rbase + fr) * 72 + cb + nt * 4 + fc] =
            pack2_e4m3(acc[nt][0] * s0, acc[nt][1] * s0);
        st16[(rbase + fr + 8) * 72 + cb + nt * 4 + fc] =
            pack2_e4m3(acc[nt][2] * s1, acc[nt][3] * s1);
    }
    __syncthreads();
    for (int i = t; i < 1024; i += 512) {
        int o = i >> 9, rem = i & 511;
        int r = rem >> 2, q = (rem & 3) << 2;
        int gr = row0 + r;
        if (gr < N) {
            u32* O = o ? O1h : O0h;
            *(uint4*)&O[((size_t)gr << 4) + q] = *(uint4*)&As[r * 36 + o * 16 + q];
        }
    }
}

#define GU_T ((NUc + 127) / 128)
#define GT_T ((NTc + 127) / 128)

__global__ void __launch_bounds__(512) transform_kernel(int l) {
    int b = blockIdx.x;
    int m = 1 + l * 4;
    if (b < GU_T) {
        dual512_gemm(g_huh, g_wpk[m + 0], g_wpk[m + 2], g_d_u2u, g_ds_u2t,
                     g_mu0h, g_mu1h, NUc, b);
    } else {
        dual512_gemm(g_hth, g_wpk[m + 1], g_wpk[m + 3], g_d_t2t, g_ds_t2u,
                     g_mt0h, g_mt1h, NTc, b - GU_T);
    }
}

// ---------------- embed_txn: fp16 MMA, 256 threads (single output) ----------------
__global__ void __launch_bounds__(256) embed_txn_kernel(const float* __restrict__ x,
                                                        const float* __restrict__ bias) {
    extern __shared__ u32 smu[];
    u32* Wf = smu;             // 2048 u32
    u32* As = smu + 2048;      // 128*36 u32
    int t = threadIdx.x;
    int lane = t & 31, wid = t >> 5;
    int fr = lane >> 2, fc = lane & 3;
    int row0 = blockIdx.x * 128;
    const int N = NTc;

    for (int i = t; i < 512; i += 256) ((uint4*)Wf)[i] = ((const uint4*)g_wpk[0])[i];
    for (int i = t; i < 128 * 32; i += 256) {
        int r = i >> 5, c = i & 31;
        int gr = row0 + r;
        u32 v = 0;
        if (gr < N) {
            const float2 f = *(const float2*)&x[((size_t)gr << 6) + 2 * c];
            __half2 h = __floats2half2_rn(f.x, f.y);
            v = *(u32*)&h;
        }
        As[r * 36 + c] = v;
    }
    __syncthreads();

    int rbase = wid * 16;
    float acc[8][4];
#pragma unroll
    for (int nt = 0; nt < 8; nt++)
#pragma unroll
        for (int j = 0; j < 4; j++) acc[nt][j] = 0.f;
#pragma unroll
    for (int kk = 0; kk < 4; kk++) {
        int abase = (rbase + fr) * 36 + kk * 8 + fc;
        u32 a0 = As[abase];
        u32 a1 = As[abase + 8 * 36];
        u32 a2 = As[abase + 4];
        u32 a3 = As[abase + 8 * 36 + 4];
#pragma unroll
        for (int nt = 0; nt < 8; nt++) {
            uint2 b = *(const uint2*)&Wf[(size_t)(((kk << 3) + nt) << 5 | lane) * 2];
            mma_f16(acc[nt], a0, a1, a2, a3, b.x, b.y);
        }
    }
    __syncthreads();
#pragma unroll
    for (int nt = 0; nt < 8; nt++) {
        float bx = bias[nt * 8 + 2 * fc], by = bias[nt * 8 + 2 * fc + 1];
        __half2 h0 = __floats2half2_rn(acc[nt][0] + bx, acc[nt][1] + by);
        __half2 h1 = __floats2half2_rn(acc[nt][2] + bx, acc[nt][3] + by);
        As[(rbase + fr) * 36 + nt * 4 + fc]     = *(u32*)&h0;
        As[(rbase + fr + 8) * 36 + nt * 4 + fc] = *(u32*)&h1;
    }
    __syncthreads();
    for (int i = t; i < 128 * 8; i += 256) {
        int r = i >> 3, q = (i & 7) << 2;
        int gr = row0 + r;
        if (gr < N) *(uint4*)&g_hth[((size_t)gr << 5) + q] = *(uint4*)&As[r * 36 + q];
    }
}

// ---------------- f32x2 embed for K=32 ----------------
__global__ void __launch_bounds__(256) embed_user_kernel(const float* __restrict__ A,
                                                         const float* __restrict__ W,
                                                         const float* __restrict__ b) {
    const int K = 32;
    __shared__ float Ws[K * 64];
    __shared__ float As[128 * (K + 1)];
    int t = threadIdx.x;
    for (int i = t; i < K * 64; i += 256) Ws[i] = W[i];
    int row0 = blockIdx.x * 128;
    for (int i = t; i < 128 * K; i += 256) {
        int r = i / K, c = i & (K - 1);
        int gr = row0 + r;
        As[r * (K + 1) + c] = (gr < NUc) ? A[(size_t)gr * K + c] : 0.f;
    }
    __syncthreads();
    int cg = t & 7, r0 = (t >> 3) << 2;
    u64 binit[4];
#pragma unroll
    for (int j = 0; j < 4; j++)
        binit[j] = pack2ab(b[(cg << 3) + (j << 1)], b[(cg << 3) + (j << 1) + 1]);
    u64 acc[4][4];
#pragma unroll
    for (int rr = 0; rr < 4; rr++)
#pragma unroll
        for (int j = 0; j < 4; j++) acc[rr][j] = binit[j];
#pragma unroll 4
    for (int k = 0; k < K; k++) {
        const float* wp = &Ws[(k << 6) + (cg << 3)];
        ulonglong2 wa = *(const ulonglong2*)wp;
        ulonglong2 wb = *(const ulonglong2*)(wp + 4);
#pragma unroll
        for (int rr = 0; rr < 4; rr++) {
            u64 a2 = pack2(As[(r0 + rr) * (K + 1) + k]);
            fma2(acc[rr][0], a2, wa.x);
            fma2(acc[rr][1], a2, wa.y);
            fma2(acc[rr][2], a2, wb.x);
            fma2(acc[rr][3], a2, wb.y);
        }
    }
#pragma unroll
    for (int rr = 0; rr < 4; rr++) {
        int gr = row0 + r0 + rr;
        if (gr < NUc) {
            float2 p0 = unpack2(acc[rr][0]), p1 = unpack2(acc[rr][1]);
            float2 p2 = unpack2(acc[rr][2]), p3 = unpack2(acc[rr][3]);
            __half2 h0 = __floats2half2_rn(p0.x, p0.y);
            __half2 h1 = __floats2half2_rn(p1.x, p1.y);
            __half2 h2 = __floats2half2_rn(p2.x, p2.y);
            __half2 h3 = __floats2half2_rn(p3.x, p3.y);
            uint4 pk;
            pk.x = *(u32*)&h0; pk.y = *(u32*)&h1; pk.z = *(u32*)&h2; pk.w = *(u32*)&h3;
            *(uint4*)&g_huh[((size_t)gr << 5) + (cg << 2)] = pk;
        }
    }
}

// ---------------- fused gather-aggregate + bias + relu (fp8 messages) ----------------
__device__ __forceinline__ void gather_loop(float* acc, const u32* __restrict__ m,
                                            const int* __restrict__ csr,
                                            int e, int end, int woff) {
    while (e < end && (e & 3)) {
        int s = __ldg(csr + e);
        acc_h8(acc, fp8_widen8(__ldg((const uint2*)(m + ((size_t)s << 4) + woff))));
        e++;
    }
    for (; e + 4 <= end; e += 4) {
        int4 s = __ldg((const int4*)(csr + e));
        uint2 v0 = __ldg((const uint2*)(m + ((size_t)s.x << 4) + woff));
        uint2 v1 = __ldg((const uint2*)(m + ((size_t)s.y << 4) + woff));
        uint2 v2 = __ldg((const uint2*)(m + ((size_t)s.z << 4) + woff));
        uint2 v3 = __ldg((const uint2*)(m + ((size_t)s.w << 4) + woff));
        uint4 x0 = fp8_widen8(v0), x1 = fp8_widen8(v1);
        uint4 x2 = fp8_widen8(v2), x3 = fp8_widen8(v3);
        uint4 tt = h2add4(h2add4(x0, x1), h2add4(x2, x3));
        acc_h8(acc, tt);
    }
    for (; e < end; e++) {
        int s = __ldg(csr + e);
        acc_h8(acc, fp8_widen8(__ldg((const uint2*)(m + ((size_t)s << 4) + woff))));
    }
}

__device__ __forceinline__ void agg_body(int idx,
                                         const u32* __restrict__ mA,
                                         const int* __restrict__ offA,
                                         const int* __restrict__ csrA,
                                         const float* __restrict__ dA,
                                         const u32* __restrict__ mB,
                                         const int* __restrict__ offB,
                                         const int* __restrict__ csrB,
                                         const float* __restrict__ dB,
                                         const float* __restrict__ bA,
                                         const float* __restrict__ bB,
                                         u32* __restrict__ Outh, int N) {
    int g = idx >> 3;
    if (g >= N) return;
    int q = idx & 7;
    int woff = q << 1;
    float a[8], b[8];
#pragma unroll
    for (int i = 0; i < 8; i++) { a[i] = 0.f; b[i] = 0.f; }
    acc_h8(a, fp8_widen8(__ldg((const uint2*)(mA + ((size_t)g << 4) + woff))));
    gather_loop(a, mA, csrA, offA[g], offA[g + 1], woff);
    gather_loop(b, mB, csrB, offB[g], offB[g + 1], woff);
    float da = dA[g], db = dB[g];
    int c0 = q << 3;
    float4 bAv0 = __ldg((const float4*)(bA + c0)), bAv1 = __ldg((const float4*)(bA + c0 + 4));
    float4 bBv0 = __ldg((const float4*)(bB + c0)), bBv1 = __ldg((const float4*)(bB + c0 + 4));
    float o0 = fmaxf(0.5f * (da * a[0] + db * b[0] + bAv0.x + bBv0.x), 0.f);
    float o1 = fmaxf(0.5f * (da * a[1] + db * b[1] + bAv0.y + bBv0.y), 0.f);
    float o2 = fmaxf(0.5f * (da * a[2] + db * b[2] + bAv0.z + bBv0.z), 0.f);
    float o3 = fmaxf(0.5f * (da * a[3] + db * b[3] + bAv0.w + bBv0.w), 0.f);
    float o4 = fmaxf(0.5f * (da * a[4] + db * b[4] + bAv1.x + bBv1.x), 0.f);
    float o5 = fmaxf(0.5f * (da * a[5] + db * b[5] + bAv1.y + bBv1.y), 0.f);
    float o6 = fmaxf(0.5f * (da * a[6] + db * b[6] + bAv1.z + bBv1.z), 0.f);
    float o7 = fmaxf(0.5f * (da * a[7] + db * b[7] + bAv1.w + bBv1.w), 0.f);
    __half2 h0 = __floats2half2_rn(o0, o1);
    __half2 h1 = __floats2half2_rn(o2, o3);
    __half2 h2 = __floats2half2_rn(o4, o5);
    __half2 h3 = __floats2half2_rn(o6, o7);
    uint4 pk;
    pk.x = *(u32*)&h0; pk.y = *(u32*)&h1; pk.z = *(u32*)&h2; pk.w = *(u32*)&h3;
    *(uint4*)&Outh[((size_t)g << 5) + (q << 2)] = pk;
}

#define AU_B ((NUc * 8 + 255) / 256)
#define AT_B ((NTc * 8 + 255) / 256)

__global__ void __launch_bounds__(256) agg_kernel(const float* __restrict__ B) {
    int b = blockIdx.x;
    if (b < AU_B) {
        agg_body(b * 256 + threadIdx.x,
                 g_mu0h, g_off_u2u, g_csr_u2u, g_d_u2u,
                 g_mt1h, g_off_t2u, g_csr_t2u, g_dd_t2u,
                 B + 0 * 64, B + 3 * 64, g_huh, NUc);
    } else {
        agg_body((b - AU_B) * 256 + threadIdx.x,
                 g_mt0h, g_off_t2t, g_csr_t2t, g_d_t2t,
                 g_mu1h, g_off_u2t, g_csr_u2t, g_dd_u2t,
                 B + 1 * 64, B + 2 * 64, g_hth, NTc);
    }
}

// ---------------- readout (fp16 h) ----------------
#define CS_BLOCKS 296
__global__ void colsum_kernel() {
    int b = blockIdx.x;
    if (b < CS_BLOCKS) {
        int t = b * blockDim.x + threadIdx.x;
        float s0 = 0.f, s1 = 0.f;
        const int n = NUc * 32;
        for (int i = t; i < n; i += CS_BLOCKS * 256) {
            u32 v = g_huh[i];
            float2 f = __half22float2(*(__half2*)&v);
            s0 += f.x; s1 += f.y;
        }
        int j = (t & 31) << 1;
        atomicAdd(&g_colsum[j], s0);
        atomicAdd(&g_colsum[j + 1], s1);
    } else {
        int t = (b - CS_BLOCKS) * blockDim.x + threadIdx.x;
        float s0 = 0.f, s1 = 0.f;
        const int n = NTc * 32;
        for (int i = t; i < n; i += CS_BLOCKS * 256) {
            u32 v = g_hth[i];
            float2 f = __half22float2(*(__half2*)&v);
            s0 += f.x; s1 += f.y;
        }
        int j = (t & 31) << 1;
        atomicAdd(&g_colsum[64 + j], s0);
        atomicAdd(&g_colsum[64 + j + 1], s1);
    }
}

__global__ void mlp_kernel(const float* __restrict__ W1, const float* __restrict__ b1,
                           const float* __restrict__ W2, const float* __restrict__ b2,
                           float* __restrict__ out) {
    __shared__ float x[64];
    __shared__ float y[64];
    int t = threadIdx.x;
    x[t] = 0.5f * (g_colsum[t] * (1.f / NUc) + g_colsum[64 + t] * (1.f / NTc));
    __syncthreads();
    float s = b1[t];
    for (int k = 0; k < 64; k++) s += x[k] * W1[k * 64 + t];
    y[t] = fmaxf(s, 0.f) * W2[t];
    __syncthreads();
    if (t == 0) {
        float o = b2[0];
        for (int j = 0; j < 64; j++) o += y[j];
        out[0] = 1.f / (1.f + expf(-o));
    }
}

// ---------------- launch ----------------
extern "C" void kernel_launch(void* const* d_in, const int* in_sizes, int n_in,
                              void* d_out, int out_size) {
    const float* x_user     = (const float*)d_in[0];
    const float* x_txn      = (const float*)d_in[1];
    const int*   ei_u2u     = (const int*)d_in[2];
    const int*   ei_t2t     = (const int*)d_in[3];
    const int*   ei_u2t     = (const int*)d_in[4];
    const int*   ei_t2u     = (const int*)d_in[5];
    const float* W_emb_user = (const float*)d_in[6];
    const float* b_emb_user = (const float*)d_in[7];
    const float* W_emb_txn  = (const float*)d_in[8];
    const float* b_emb_txn  = (const float*)d_in[9];
    const float* conv_W     = (const float*)d_in[10];
    const float* conv_b     = (const float*)d_in[11];
    const float* W1         = (const float*)d_in[12];
    const float* b1         = (const float*)d_in[13];
    const float* W2         = (const float*)d_in[14];
    const float* b2         = (const float*)d_in[15];
    float* out = (float*)d_out;

    const int SMEM_DUAL = (4096 + 128 * 36) * 4;   // 34816
    const int SMEM_SNGL = (2048 + 128 * 36) * 4;   // 26624

    packw_kernel<<<13, 256>>>(W_emb_txn, conv_W);
    zero_cnt_kernel<<<(NTc + 255) / 256, 256>>>();
    count_kernel<<<(Ec + 255) / 256, 256>>>(ei_u2u, ei_t2t, ei_u2t, ei_t2u);
    embed_txn_kernel<<<GT_T, 256, SMEM_SNGL>>>(x_txn, b_emb_txn);
    embed_user_kernel<<<(NUc + 127) / 128, 256>>>(x_user, W_emb_user, b_emb_user);
    scan4_kernel<<<4, 1024>>>();
    fill_kernel<<<(Ec + 255) / 256, 256>>>(ei_u2u, ei_t2t, ei_u2t, ei_t2u);
    dinv_kernel<<<(NTc + 255) / 256, 256>>>();

    // ---- layers ----
    for (int l = 0; l < 3; l++) {
        const float* B = conv_b + (size_t)l * 4 * 64;
        transform_kernel<<<GU_T + GT_T, 512, SMEM_DUAL>>>(l);
        agg_kernel<<<AU_B + AT_B, 256>>>(B);
    }

    // ---- readout ----
    colsum_kernel<<<2 * CS_BLOCKS, 256>>>();
    mlp_kernel<<<1, 64>>>(W1, b1, W2, b2, out);
}